// round 2
// baseline (speedup 1.0000x reference)
#include <cuda_runtime.h>

#define H 512
#define W 512
#define HW (H * W)
#define BN_EPS 1e-5f

typedef unsigned long long u64;

// Precomputed effective weights (written by prep_kernel each launch).
__device__ float g_Weff[675];   // [(c*5+u)*5+v]*9+k : scaled 5x5 weights on input
__device__ float g_W0[243];     // [(j*3+u)*3+v]*9+k : scaled 3x3 weights on input0
__device__ float g_Shift[9];    // BN shift per k

// ---------------- packed f32x2 helpers ----------------
__device__ __forceinline__ u64 pk(float a, float b) {
    u64 d;
    asm("mov.b64 %0, {%1, %2};" : "=l"(d) : "f"(a), "f"(b));
    return d;
}
__device__ __forceinline__ void upk(u64 d, float& a, float& b) {
    asm("mov.b64 {%0, %1}, %2;" : "=f"(a), "=f"(b) : "l"(d));
}
__device__ __forceinline__ void fma2(u64& c, u64 a, u64 b) {
    asm("fma.rn.f32x2 %0, %1, %2, %0;" : "+l"(c) : "l"(a), "l"(b));
}
__device__ __forceinline__ u64 add2(u64 a, u64 b) {
    u64 d;
    asm("add.rn.f32x2 %0, %1, %2;" : "=l"(d) : "l"(a), "l"(b));
    return d;
}

// ---------------------------------------------------------------------------
// Kernel 1: fold im2col+conv into effective 5x5 / 3x3 weights, fold BN scale.
// ---------------------------------------------------------------------------
__global__ void prep_kernel(const float* __restrict__ cw,
                            const float* __restrict__ gam,
                            const float* __restrict__ bet,
                            const float* __restrict__ mu,
                            const float* __restrict__ var) {
    int tid = threadIdx.x;
    if (tid < 675) {
        int k = tid % 9;
        int rest = tid / 9;
        int v = rest % 5; rest /= 5;
        int u = rest % 5;
        int c = rest / 5;
        float s = gam[k] * rsqrtf(var[k] + BN_EPS);
        float sum = 0.f;
        for (int ti = 0; ti < 3; ti++) {
            int di = u - ti;
            if (di < 0 || di > 2) continue;
            for (int tj = 0; tj < 3; tj++) {
                int dj = v - tj;
                if (dj < 0 || dj > 2) continue;
                int t = ti * 3 + tj;
                if (c == 0 && t >= 4 && t <= 6) continue;  // replaced rows
                sum += cw[((k * 27 + c * 9 + t) * 3 + di) * 3 + dj];
            }
        }
        g_Weff[tid] = s * sum;
    } else if (tid < 675 + 243) {
        int i = tid - 675;
        int k = i % 9;
        int rest = i / 9;
        int v = rest % 3; rest /= 3;
        int u = rest % 3;
        int j = rest / 3;
        float s = gam[k] * rsqrtf(var[k] + BN_EPS);
        g_W0[i] = s * cw[((k * 27 + 4 + j) * 3 + u) * 3 + v];
    } else if (tid < 675 + 243 + 9) {
        int k = tid - 918;
        float s = gam[k] * rsqrtf(var[k] + BN_EPS);
        g_Shift[k] = bet[k] - mu[k] * s;
    }
}

// ---------------------------------------------------------------------------
// Load a 12-wide window [w0-2, w0+9] from one row into packed pairs:
//   e[i] = {v[2i], v[2i+1]}   (even pairs, free from aligned float2 loads)
//   o[i] = {v[2i+1], v[2i+2]} (odd pairs, built via mov.b64)
// ---------------------------------------------------------------------------
__device__ __forceinline__ void load_row12(const float* __restrict__ rowp, int w0,
                                           bool rowok, bool colsafe,
                                           u64 e[6], u64 o[5]) {
    float v[12];
    if (rowok && colsafe) {
        // w0 multiple of 8 -> w0-2 even -> 8B-aligned 64-bit loads.
#pragma unroll
        for (int i = 0; i < 6; i++)
            e[i] = *(const u64*)(rowp + w0 - 2 + 2 * i);
#pragma unroll
        for (int i = 0; i < 6; i++) upk(e[i], v[2 * i], v[2 * i + 1]);
    } else if (rowok) {
#pragma unroll
        for (int i = 0; i < 12; i++) {
            int ww = w0 - 2 + i;
            v[i] = (ww >= 0 && ww < W) ? rowp[ww] : 0.f;
        }
#pragma unroll
        for (int i = 0; i < 6; i++) e[i] = pk(v[2 * i], v[2 * i + 1]);
    } else {
#pragma unroll
        for (int i = 0; i < 12; i++) v[i] = 0.f;
#pragma unroll
        for (int i = 0; i < 6; i++) e[i] = 0ull;
    }
#pragma unroll
    for (int i = 0; i < 5; i++) o[i] = pk(v[2 * i + 1], v[2 * i + 2]);
}

// ---------------------------------------------------------------------------
// Kernel 2: main fused kernel. Block = 8x16 threads, each thread -> 8 pixels
// along w (4 packed pairs). Tile = 64x16 pixels.
// ---------------------------------------------------------------------------
__global__ __launch_bounds__(128) void cspn_main(const float* __restrict__ ker,
                                                 const float* __restrict__ in,
                                                 const float* __restrict__ in0,
                                                 float* __restrict__ out) {
    __shared__ float2 sW[675];   // duplicated {w,w}
    __shared__ float2 s0[243];
    __shared__ u64 sS[9];        // duplicated {sh,sh}

    int tid = threadIdx.y * 8 + threadIdx.x;
    for (int i = tid; i < 675; i += 128) { float wv = g_Weff[i]; sW[i] = make_float2(wv, wv); }
    for (int i = tid; i < 243; i += 128) { float wv = g_W0[i];   s0[i] = make_float2(wv, wv); }
    if (tid < 9) { float sh = g_Shift[tid]; sS[tid] = pk(sh, sh); }
    __syncthreads();

    const int b  = blockIdx.z;
    const int h  = blockIdx.y * 16 + threadIdx.y;
    const int w0 = blockIdx.x * 64 + threadIdx.x * 8;

    u64 acc[9][4];
#pragma unroll
    for (int k = 0; k < 9; k++)
#pragma unroll
        for (int j = 0; j < 4; j++) acc[k][j] = 0ull;

    const bool colsafe = (w0 >= 2) && (w0 + 10 <= W);
    const float* inb  = in  + (size_t)b * 3 * HW;
    const float* in0b = in0 + (size_t)b * 3 * HW;

    // ---- effective 5x5 conv on input (3 channels) ----
    // data index (rel. to w0-2) for (v,pair j) = v + 2j
#pragma unroll 1
    for (int c = 0; c < 3; c++) {
        const float* inc = inb + c * HW;
#pragma unroll 1
        for (int u = 0; u < 5; u++) {
            int r = h + u - 2;
            u64 e[6], o[5];
            load_row12(inc + r * W, w0, (r >= 0 && r < H), colsafe, e, o);
            const float2* wp = &sW[(c * 5 + u) * 45];
#pragma unroll
            for (int v = 0; v < 5; v++) {
                const u64* src = (v & 1) ? &o[(v - 1) >> 1] : &e[v >> 1];
#pragma unroll
                for (int k = 0; k < 9; k++) {
                    u64 w2 = *(const u64*)&wp[v * 9 + k];   // LDS.64 broadcast
                    fma2(acc[k][0], w2, src[0]);
                    fma2(acc[k][1], w2, src[1]);
                    fma2(acc[k][2], w2, src[2]);
                    fma2(acc[k][3], w2, src[3]);
                }
            }
        }
    }

    // ---- 3x3 conv on input0 (replaced channels 4..6) ----
    // data index = 1 + v + 2j
#pragma unroll 1
    for (int j3 = 0; j3 < 3; j3++) {
        const float* inc = in0b + j3 * HW;
#pragma unroll 1
        for (int u = 0; u < 3; u++) {
            int r = h + u - 1;
            u64 e[6], o[5];
            load_row12(inc + r * W, w0, (r >= 0 && r < H), colsafe, e, o);
            const float2* wp = &s0[(j3 * 3 + u) * 27];
#pragma unroll
            for (int v = 0; v < 3; v++) {
                int idx = 1 + v;  // 1,2,3
                const u64* src = (idx & 1) ? &o[(idx - 1) >> 1] : &e[idx >> 1];
#pragma unroll
                for (int k = 0; k < 9; k++) {
                    u64 w2 = *(const u64*)&wp[v * 9 + k];
                    fma2(acc[k][0], w2, src[0]);
                    fma2(acc[k][1], w2, src[1]);
                    fma2(acc[k][2], w2, src[2]);
                    fma2(acc[k][3], w2, src[3]);
                }
            }
        }
    }

    // ---- epilogue: per-pixel dot with kernel, plus BN shift ----
    u64 r[4] = {0ull, 0ull, 0ull, 0ull};
    const float* kp = ker + (size_t)b * 9 * HW + h * W + w0;
#pragma unroll
    for (int k = 0; k < 9; k++) {
        float4 ka = *(const float4*)(kp + k * HW);
        float4 kb = *(const float4*)(kp + k * HW + 4);
        u64 sh2 = sS[k];
        u64 t0 = add2(acc[k][0], sh2);
        u64 t1 = add2(acc[k][1], sh2);
        u64 t2 = add2(acc[k][2], sh2);
        u64 t3 = add2(acc[k][3], sh2);
        fma2(r[0], pk(ka.x, ka.y), t0);
        fma2(r[1], pk(ka.z, ka.w), t1);
        fma2(r[2], pk(kb.x, kb.y), t2);
        fma2(r[3], pk(kb.z, kb.w), t3);
    }
    float o0, o1, o2, o3, o4, o5, o6, o7;
    upk(r[0], o0, o1); upk(r[1], o2, o3); upk(r[2], o4, o5); upk(r[3], o6, o7);
    float* op = out + (size_t)b * HW + h * W + w0;
    *(float4*)(op)     = make_float4(o0, o1, o2, o3);
    *(float4*)(op + 4) = make_float4(o4, o5, o6, o7);
}

// ---------------------------------------------------------------------------
// Kernel 3: exact path for the 1-pixel ring (double zero-pad semantics).
// Overwrites the ring outputs written (incorrectly) by cspn_main.
// ---------------------------------------------------------------------------
__global__ void border_kernel(const float* __restrict__ ker,
                              const float* __restrict__ in,
                              const float* __restrict__ in0,
                              const float* __restrict__ cw,
                              const float* __restrict__ gam,
                              const float* __restrict__ bet,
                              const float* __restrict__ mu,
                              const float* __restrict__ var,
                              float* __restrict__ out, int total) {
    __shared__ float sw[2187];
    for (int i = threadIdx.x; i < 2187; i += blockDim.x) sw[i] = cw[i];
    __syncthreads();

    int gid = blockIdx.x * blockDim.x + threadIdx.x;
    if (gid >= total) return;

    const int RING = 4 * W - 4;  // 2044
    int b = gid / RING, pos = gid % RING;
    int h, w;
    if (pos < W)            { h = 0;       w = pos; }
    else if (pos < 2 * W)   { h = H - 1;   w = pos - W; }
    else {
        int p2 = pos - 2 * W;
        h = 1 + (p2 >> 1);
        w = (p2 & 1) ? (W - 1) : 0;
    }

    float acc[9];
#pragma unroll
    for (int k = 0; k < 9; k++) acc[k] = 0.f;

    const float* inb  = in  + (size_t)b * 3 * HW;
    const float* in0b = in0 + (size_t)b * 3 * HW;

#pragma unroll 1
    for (int dy = -1; dy <= 1; dy++) {
#pragma unroll 1
        for (int dx = -1; dx <= 1; dx++) {
            int qy = h + dy, qx = w + dx;
            if (qy < 0 || qy >= H || qx < 0 || qx >= W) continue;  // x zero-pad
            int didx = (dy + 1) * 3 + (dx + 1);
#pragma unroll 1
            for (int ch = 0; ch < 27; ch++) {
                float val;
                if (ch >= 4 && ch <= 6) {
                    val = in0b[(ch - 4) * HW + qy * W + qx];
                } else {
                    int c = ch / 9, t = ch % 9;
                    int py = qy + t / 3 - 1, px = qx + t % 3 - 1;
                    val = (py >= 0 && py < H && px >= 0 && px < W)
                              ? inb[c * HW + py * W + px] : 0.f;
                }
#pragma unroll
                for (int k = 0; k < 9; k++)
                    acc[k] = fmaf(sw[(k * 27 + ch) * 9 + didx], val, acc[k]);
            }
        }
    }

    float r = 0.f;
#pragma unroll
    for (int k = 0; k < 9; k++) {
        float s  = gam[k] * rsqrtf(var[k] + BN_EPS);
        float sh = bet[k] - mu[k] * s;
        r = fmaf(ker[((size_t)b * 9 + k) * HW + h * W + w], fmaf(s, acc[k], sh), r);
    }
    out[(size_t)b * HW + h * W + w] = r;
}

// ---------------------------------------------------------------------------
extern "C" void kernel_launch(void* const* d_in, const int* in_sizes, int n_in,
                              void* d_out, int out_size) {
    const float* ker = (const float*)d_in[0];
    const float* in  = (const float*)d_in[1];
    const float* in0 = (const float*)d_in[2];
    const float* cw  = (const float*)d_in[3];
    const float* gam = (const float*)d_in[4];
    const float* bet = (const float*)d_in[5];
    const float* mu  = (const float*)d_in[6];
    const float* var = (const float*)d_in[7];
    float* out = (float*)d_out;

    int bs = in_sizes[0] / (9 * HW);   // batch from kernel tensor size

    prep_kernel<<<1, 1024>>>(cw, gam, bet, mu, var);

    dim3 blk(8, 16);
    dim3 grd(W / 64, H / 16, bs);
    cspn_main<<<grd, blk>>>(ker, in, in0, out);

    int ring_total = bs * (4 * W - 4);
    int nb = (ring_total + 127) / 128;
    border_kernel<<<nb, 128>>>(ker, in, in0, cw, gam, bet, mu, var, out, ring_total);
}

// round 3
// speedup vs baseline: 1.1494x; 1.1494x over previous
#include <cuda_runtime.h>

#define H 512
#define W 512
#define HW (H * W)
#define BN_EPS 1e-5f

typedef unsigned long long u64;

// Precomputed effective weights (written by prep_kernel each launch).
__device__ float g_Weff[675];   // [(c*5+u)*5+v]*9+k : scaled 5x5 weights on input
__device__ float g_W0[243];     // [(j*3+u)*3+v]*9+k : scaled 3x3 weights on input0
__device__ float g_Shift[9];    // BN shift per k

// ---------------- packed f32x2 helpers ----------------
__device__ __forceinline__ u64 pk(float a, float b) {
    u64 d;
    asm("mov.b64 %0, {%1, %2};" : "=l"(d) : "f"(a), "f"(b));
    return d;
}
__device__ __forceinline__ void upk(u64 d, float& a, float& b) {
    asm("mov.b64 {%0, %1}, %2;" : "=f"(a), "=f"(b) : "l"(d));
}
__device__ __forceinline__ void fma2(u64& c, u64 a, u64 b) {
    asm("fma.rn.f32x2 %0, %1, %2, %0;" : "+l"(c) : "l"(a), "l"(b));
}
__device__ __forceinline__ u64 add2(u64 a, u64 b) {
    u64 d;
    asm("add.rn.f32x2 %0, %1, %2;" : "=l"(d) : "l"(a), "l"(b));
    return d;
}

// ---------------------------------------------------------------------------
// Kernel 1: fold im2col+conv into effective 5x5 / 3x3 weights, fold BN scale.
// ---------------------------------------------------------------------------
__global__ void prep_kernel(const float* __restrict__ cw,
                            const float* __restrict__ gam,
                            const float* __restrict__ bet,
                            const float* __restrict__ mu,
                            const float* __restrict__ var) {
    int tid = threadIdx.x;
    if (tid < 675) {
        int k = tid % 9;
        int rest = tid / 9;
        int v = rest % 5; rest /= 5;
        int u = rest % 5;
        int c = rest / 5;
        float s = gam[k] * rsqrtf(var[k] + BN_EPS);
        float sum = 0.f;
        for (int ti = 0; ti < 3; ti++) {
            int di = u - ti;
            if (di < 0 || di > 2) continue;
            for (int tj = 0; tj < 3; tj++) {
                int dj = v - tj;
                if (dj < 0 || dj > 2) continue;
                int t = ti * 3 + tj;
                if (c == 0 && t >= 4 && t <= 6) continue;  // replaced rows
                sum += cw[((k * 27 + c * 9 + t) * 3 + di) * 3 + dj];
            }
        }
        g_Weff[tid] = s * sum;
    } else if (tid < 675 + 243) {
        int i = tid - 675;
        int k = i % 9;
        int rest = i / 9;
        int v = rest % 3; rest /= 3;
        int u = rest % 3;
        int j = rest / 3;
        float s = gam[k] * rsqrtf(var[k] + BN_EPS);
        g_W0[i] = s * cw[((k * 27 + 4 + j) * 3 + u) * 3 + v];
    } else if (tid < 675 + 243 + 9) {
        int k = tid - 918;
        float s = gam[k] * rsqrtf(var[k] + BN_EPS);
        g_Shift[k] = bet[k] - mu[k] * s;
    }
}

// ---------------------------------------------------------------------------
// Load an 8-wide window [w0-2, w0+5] from one row into packed pairs:
//   e[i] = {v[2i], v[2i+1]}   i=0..3 (even pairs, from aligned 64-bit loads)
//   o[i] = {v[2i+1], v[2i+2]} i=0..2 (odd pairs, built via mov.b64)
// ---------------------------------------------------------------------------
__device__ __forceinline__ void load_row8(const float* __restrict__ rowp, int w0,
                                          bool rowok, bool colsafe,
                                          u64 e[4], u64 o[3]) {
    float v[8];
    if (rowok && colsafe) {
        // w0 multiple of 4 -> w0-2 even -> 8B-aligned 64-bit loads.
#pragma unroll
        for (int i = 0; i < 4; i++)
            e[i] = *(const u64*)(rowp + w0 - 2 + 2 * i);
#pragma unroll
        for (int i = 0; i < 4; i++) upk(e[i], v[2 * i], v[2 * i + 1]);
    } else if (rowok) {
#pragma unroll
        for (int i = 0; i < 8; i++) {
            int ww = w0 - 2 + i;
            v[i] = (ww >= 0 && ww < W) ? rowp[ww] : 0.f;
        }
#pragma unroll
        for (int i = 0; i < 4; i++) e[i] = pk(v[2 * i], v[2 * i + 1]);
    } else {
#pragma unroll
        for (int i = 0; i < 8; i++) v[i] = 0.f;
#pragma unroll
        for (int i = 0; i < 4; i++) e[i] = 0ull;
    }
#pragma unroll
    for (int i = 0; i < 3; i++) o[i] = pk(v[2 * i + 1], v[2 * i + 2]);
}

// ---------------------------------------------------------------------------
// Kernel 2: main fused kernel. Block = 8x16 threads, each thread -> 4 pixels
// along w (2 packed pairs). Tile = 32x16 pixels.
// ---------------------------------------------------------------------------
__global__ __launch_bounds__(128) void cspn_main(const float* __restrict__ ker,
                                                 const float* __restrict__ in,
                                                 const float* __restrict__ in0,
                                                 float* __restrict__ out) {
    __shared__ float2 sW[675];   // duplicated {w,w}
    __shared__ float2 s0[243];
    __shared__ u64 sS[9];        // duplicated {sh,sh}

    int tid = threadIdx.y * 8 + threadIdx.x;
    for (int i = tid; i < 675; i += 128) { float wv = g_Weff[i]; sW[i] = make_float2(wv, wv); }
    for (int i = tid; i < 243; i += 128) { float wv = g_W0[i];   s0[i] = make_float2(wv, wv); }
    if (tid < 9) { float sh = g_Shift[tid]; sS[tid] = pk(sh, sh); }
    __syncthreads();

    const int b  = blockIdx.z;
    const int h  = blockIdx.y * 16 + threadIdx.y;
    const int w0 = blockIdx.x * 32 + threadIdx.x * 4;

    u64 acc[9][2];
#pragma unroll
    for (int k = 0; k < 9; k++) { acc[k][0] = 0ull; acc[k][1] = 0ull; }

    const bool colsafe = (w0 >= 2) && (w0 + 6 <= W);
    const float* inb  = in  + (size_t)b * 3 * HW;
    const float* in0b = in0 + (size_t)b * 3 * HW;

    // ---- effective 5x5 conv on input (3 channels) ----
    // data index (rel. to w0-2) for (v, pair j) = v + 2j, v in 0..4, j in 0..1
#pragma unroll 1
    for (int c = 0; c < 3; c++) {
        const float* inc = inb + c * HW;
#pragma unroll 1
        for (int u = 0; u < 5; u++) {
            int r = h + u - 2;
            u64 e[4], o[3];
            load_row8(inc + r * W, w0, (r >= 0 && r < H), colsafe, e, o);
            const float2* wp = &sW[(c * 5 + u) * 45];
#pragma unroll
            for (int v = 0; v < 5; v++) {
                u64 d0 = (v & 1) ? o[(v - 1) >> 1] : e[v >> 1];           // idx v
                u64 d1 = (v & 1) ? o[(v + 1) >> 1] : e[(v + 2) >> 1];     // idx v+2
#pragma unroll
                for (int k = 0; k < 9; k++) {
                    u64 w2 = *(const u64*)&wp[v * 9 + k];   // LDS.64 broadcast
                    fma2(acc[k][0], w2, d0);
                    fma2(acc[k][1], w2, d1);
                }
            }
        }
    }

    // ---- 3x3 conv on input0 (replaced channels 4..6) ----
    // data index = 1 + v + 2j, v in 0..2
#pragma unroll 1
    for (int j3 = 0; j3 < 3; j3++) {
        const float* inc = in0b + j3 * HW;
#pragma unroll 1
        for (int u = 0; u < 3; u++) {
            int r = h + u - 1;
            u64 e[4], o[3];
            load_row8(inc + r * W, w0, (r >= 0 && r < H), colsafe, e, o);
            const float2* wp = &s0[(j3 * 3 + u) * 27];
#pragma unroll
            for (int v = 0; v < 3; v++) {
                int i0 = 1 + v;       // 1,2,3
                u64 d0 = (i0 & 1) ? o[(i0 - 1) >> 1] : e[i0 >> 1];
                int i1 = 3 + v;       // 3,4,5
                u64 d1 = (i1 & 1) ? o[(i1 - 1) >> 1] : e[i1 >> 1];
#pragma unroll
                for (int k = 0; k < 9; k++) {
                    u64 w2 = *(const u64*)&wp[v * 9 + k];
                    fma2(acc[k][0], w2, d0);
                    fma2(acc[k][1], w2, d1);
                }
            }
        }
    }

    // ---- epilogue: per-pixel dot with kernel, plus BN shift ----
    u64 r0 = 0ull, r1 = 0ull;
    const float* kp = ker + (size_t)b * 9 * HW + h * W + w0;
#pragma unroll
    for (int k = 0; k < 9; k++) {
        float4 kv = *(const float4*)(kp + k * HW);
        u64 sh2 = sS[k];
        fma2(r0, pk(kv.x, kv.y), add2(acc[k][0], sh2));
        fma2(r1, pk(kv.z, kv.w), add2(acc[k][1], sh2));
    }
    float o0, o1, o2, o3;
    upk(r0, o0, o1); upk(r1, o2, o3);
    *(float4*)(out + (size_t)b * HW + h * W + w0) = make_float4(o0, o1, o2, o3);
}

// ---------------------------------------------------------------------------
// Kernel 3: exact path for the 1-pixel ring (double zero-pad semantics).
// Overwrites the ring outputs written (incorrectly) by cspn_main.
// ---------------------------------------------------------------------------
__global__ void border_kernel(const float* __restrict__ ker,
                              const float* __restrict__ in,
                              const float* __restrict__ in0,
                              const float* __restrict__ cw,
                              const float* __restrict__ gam,
                              const float* __restrict__ bet,
                              const float* __restrict__ mu,
                              const float* __restrict__ var,
                              float* __restrict__ out, int total) {
    __shared__ float sw[2187];
    for (int i = threadIdx.x; i < 2187; i += blockDim.x) sw[i] = cw[i];
    __syncthreads();

    int gid = blockIdx.x * blockDim.x + threadIdx.x;
    if (gid >= total) return;

    const int RING = 4 * W - 4;  // 2044
    int b = gid / RING, pos = gid % RING;
    int h, w;
    if (pos < W)            { h = 0;       w = pos; }
    else if (pos < 2 * W)   { h = H - 1;   w = pos - W; }
    else {
        int p2 = pos - 2 * W;
        h = 1 + (p2 >> 1);
        w = (p2 & 1) ? (W - 1) : 0;
    }

    float acc[9];
#pragma unroll
    for (int k = 0; k < 9; k++) acc[k] = 0.f;

    const float* inb  = in  + (size_t)b * 3 * HW;
    const float* in0b = in0 + (size_t)b * 3 * HW;

#pragma unroll 1
    for (int dy = -1; dy <= 1; dy++) {
#pragma unroll 1
        for (int dx = -1; dx <= 1; dx++) {
            int qy = h + dy, qx = w + dx;
            if (qy < 0 || qy >= H || qx < 0 || qx >= W) continue;  // x zero-pad
            int didx = (dy + 1) * 3 + (dx + 1);
#pragma unroll 1
            for (int ch = 0; ch < 27; ch++) {
                float val;
                if (ch >= 4 && ch <= 6) {
                    val = in0b[(ch - 4) * HW + qy * W + qx];
                } else {
                    int c = ch / 9, t = ch % 9;
                    int py = qy + t / 3 - 1, px = qx + t % 3 - 1;
                    val = (py >= 0 && py < H && px >= 0 && px < W)
                              ? inb[c * HW + py * W + px] : 0.f;
                }
#pragma unroll
                for (int k = 0; k < 9; k++)
                    acc[k] = fmaf(sw[(k * 27 + ch) * 9 + didx], val, acc[k]);
            }
        }
    }

    float r = 0.f;
#pragma unroll
    for (int k = 0; k < 9; k++) {
        float s  = gam[k] * rsqrtf(var[k] + BN_EPS);
        float sh = bet[k] - mu[k] * s;
        r = fmaf(ker[((size_t)b * 9 + k) * HW + h * W + w], fmaf(s, acc[k], sh), r);
    }
    out[(size_t)b * HW + h * W + w] = r;
}

// ---------------------------------------------------------------------------
extern "C" void kernel_launch(void* const* d_in, const int* in_sizes, int n_in,
                              void* d_out, int out_size) {
    const float* ker = (const float*)d_in[0];
    const float* in  = (const float*)d_in[1];
    const float* in0 = (const float*)d_in[2];
    const float* cw  = (const float*)d_in[3];
    const float* gam = (const float*)d_in[4];
    const float* bet = (const float*)d_in[5];
    const float* mu  = (const float*)d_in[6];
    const float* var = (const float*)d_in[7];
    float* out = (float*)d_out;

    int bs = in_sizes[0] / (9 * HW);   // batch from kernel tensor size

    prep_kernel<<<1, 1024>>>(cw, gam, bet, mu, var);

    dim3 blk(8, 16);
    dim3 grd(W / 32, H / 16, bs);
    cspn_main<<<grd, blk>>>(ker, in, in0, out);

    int ring_total = bs * (4 * W - 4);
    int nb = (ring_total + 127) / 128;
    border_kernel<<<nb, 128>>>(ker, in, in0, cw, gam, bet, mu, var, out, ring_total);
}